// round 7
// baseline (speedup 1.0000x reference)
#include <cuda_runtime.h>
#include <cuda_bf16.h>
#include <math.h>
#include <stdint.h>

#define N_SAMPLES 16384
#define F_DIM 64
#define K_BINS 32
#define M_DIM 2048
#define C_DIM 128
#define EPSV 1e-8f
#define SPLITS 16
#define L_CHUNK 1024
#define NIT 32            // chunks of 32 samples

// ---- k1 dynamic smem layout (bytes) ----
#define OFF_RAW  0        // 2 x [32][132] fp32 membership  = 33792
#define OFF_A    33792    // 2 x [8][136] u32 quantized A   = 8704
#define OFF_B    42496    // 2 x [8][136] u32 quantized B   = 8704
#define OFF_YQ   51200    // 2 x 32B ysq u8 quads
#define OFF_RED  51264    // 256 floats reduction
#define SMEM_K1  52288

#define INV255   (1.0f / 255.0f)
#define INV65025 (1.0f / 65025.0f)
#define WY_SCALE (128.0f / 65025.0f)

__device__ float    gS[M_DIM * C_DIM];
__device__ float    gMass[M_DIM];
__device__ float    gWy[M_DIM];
__device__ uint32_t gTq[(N_SAMPLES / 4) * C_DIM];   // teacher u8, k-quads x c
__device__ uint32_t gYsqQ[N_SAMPLES / 4];           // ysq u8 (scale 255/128), quads
__device__ float    gOut[4];
__device__ int      gDone;

__device__ __forceinline__ float warp_sum(float v) {
    v += __shfl_xor_sync(0xffffffffu, v, 16);
    v += __shfl_xor_sync(0xffffffffu, v, 8);
    v += __shfl_xor_sync(0xffffffffu, v, 4);
    v += __shfl_xor_sync(0xffffffffu, v, 2);
    v += __shfl_xor_sync(0xffffffffu, v, 1);
    return v;
}

// round(v*255) into low byte via 2^23 magic (v in [0,1])
__device__ __forceinline__ uint32_t q255(float v) {
    return __float_as_uint(fmaf(v, 255.0f, 8388608.0f));
}
__device__ __forceinline__ uint32_t pack4(uint32_t u0, uint32_t u1,
                                          uint32_t u2, uint32_t u3) {
    uint32_t b01 = __byte_perm(u0, u1, 0x0040);
    uint32_t b23 = __byte_perm(u2, u3, 0x0040);
    return __byte_perm(b01, b23, 0x5410);
}
__device__ __forceinline__ uint32_t dp4a_u(uint32_t a, uint32_t b, uint32_t c) {
    uint32_t r;
    asm("dp4a.u32.u32 %0, %1, %2, %3;" : "=r"(r) : "r"(a), "r"(b), "r"(c));
    return r;
}

__device__ __forceinline__ void mma_u8(int* d, const uint32_t* a,
                                       uint32_t b0, uint32_t b1) {
    asm volatile(
        "mma.sync.aligned.m16n8k32.row.col.s32.u8.u8.s32 "
        "{%0,%1,%2,%3}, {%4,%5,%6,%7}, {%8,%9}, {%0,%1,%2,%3};\n"
        : "+r"(d[0]), "+r"(d[1]), "+r"(d[2]), "+r"(d[3])
        : "r"(a[0]), "r"(a[1]), "r"(a[2]), "r"(a[3]), "r"(b0), "r"(b1));
}

__device__ __forceinline__ void cp16(uint32_t dst, const void* src) {
    asm volatile("cp.async.cg.shared.global [%0], [%1], 16;\n" :: "r"(dst), "l"(src));
}

// ---------------- Kernel 0: zero + quantize teacher (transposed quads) + ysq ----------------
__global__ void __launch_bounds__(256) k0_init(const float* __restrict__ teacher) {
    __shared__ float T[64][132];
    __shared__ float s_ysq[64];
    int tid = threadIdx.x;
    int b = blockIdx.x;            // 0..255, 64 samples each
    int idx = b * 256 + tid;

    reinterpret_cast<uint4*>(gS)[idx] = make_uint4(0, 0, 0, 0);   // 1MB zero
    if (b < 8) { gMass[b * 256 + tid] = 0.0f; gWy[b * 256 + tid] = 0.0f; }
    if (idx < 4) gOut[idx] = 0.0f;
    if (idx == 4) gDone = 0;

    int n0 = b * 64;
#pragma unroll
    for (int r = 0; r < 8; ++r) {
        int i = tid + 256 * r;
        int n = i >> 5, c4 = i & 31;
        float4 v = reinterpret_cast<const float4*>(teacher)[(size_t)(n0 + n) * 32 + c4];
        *reinterpret_cast<float4*>(&T[n][c4 * 4]) = v;
    }
    __syncthreads();

    int w = tid >> 5, lane = tid & 31;
#pragma unroll
    for (int r = 0; r < 8; ++r) {
        int n = w + 8 * r;
        float s = 0.0f;
#pragma unroll
        for (int j = 0; j < 4; ++j) { float v = T[n][lane + 32 * j]; s += v * v; }
        s = warp_sum(s);
        if (lane == 0) s_ysq[n] = s;
    }
    __syncthreads();

    // quantize teacher into k-quads: gTq[nq][c]
    int c = tid & 127, h = tid >> 7;
#pragma unroll
    for (int i = 0; i < 8; ++i) {
        int nql = h * 8 + i;        // 0..15
        int nb = nql * 4;
        uint32_t pk = pack4(q255(T[nb + 0][c]), q255(T[nb + 1][c]),
                            q255(T[nb + 2][c]), q255(T[nb + 3][c]));
        gTq[(size_t)(b * 16 + nql) * C_DIM + c] = pk;
    }
    // quantize ysq (scale 255/128)
    if (tid < 16) {
        const float ys = 255.0f / 128.0f;
        uint32_t pk = pack4(
            __float_as_uint(fmaf(s_ysq[4 * tid + 0], ys, 8388608.0f)),
            __float_as_uint(fmaf(s_ysq[4 * tid + 1], ys, 8388608.0f)),
            __float_as_uint(fmaf(s_ysq[4 * tid + 2], ys, 8388608.0f)),
            __float_as_uint(fmaf(s_ysq[4 * tid + 3], ys, 8388608.0f)));
        gYsqQ[b * 16 + tid] = pk;
    }
}

// ---------------- Kernel 1: u8 IMMA GEMM + fused quantize + dp4a mass/wy ----------------
__global__ void __launch_bounds__(256, 2)
k1_main(const float* __restrict__ membership) {
    extern __shared__ char smem[];
    uint32_t sb = (uint32_t)__cvta_generic_to_shared(smem);

    int tid = threadIdx.x;
    int mt = blockIdx.x & 15;
    int sp = blockIdx.x >> 4;
    int m0 = mt * 128;
    int nbeg = sp * L_CHUNK;

    int w = tid >> 5, lane = tid & 31;
    int m_off = (w & 3) * 32;
    int c_off = (w >> 2) * 64;
    int lr = lane >> 2, lc = lane & 3;
    int m_own = tid & 127, h = tid >> 7;

    int d[2][8][4];
#pragma unroll
    for (int i = 0; i < 2; ++i)
#pragma unroll
        for (int j = 0; j < 8; ++j)
#pragma unroll
            for (int t = 0; t < 4; ++t) d[i][j][t] = 0;
    uint32_t massI = 0u, wyI = 0u;

    auto stage = [&](int it, int buf) {
        int n0 = nbeg + it * 32;
        // raw membership fp32: 32 rows x 128 floats, [n][132] layout
#pragma unroll
        for (int r = 0; r < 4; ++r) {
            int i = tid + 256 * r;
            int n = i >> 5, ch = i & 31;
            cp16(sb + OFF_RAW + buf * 16896 + (n * 132 + ch * 4) * 4,
                 membership + (size_t)(n0 + n) * M_DIM + m0 + ch * 4);
        }
        // B quads from gTq: [8][136] u32
        {
            int nq0 = n0 >> 2;
            int nq = tid >> 5, c4 = tid & 31;
            cp16(sb + OFF_B + buf * 4352 + (nq * 136 + c4 * 4) * 4,
                 gTq + (size_t)(nq0 + nq) * C_DIM + c4 * 4);
            if (tid < 2)
                cp16(sb + OFF_YQ + buf * 32 + tid * 16, gYsqQ + nq0 + tid * 4);
        }
    };

    stage(0, 0);
    asm volatile("cp.async.commit_group;\n");

    for (int it = 0; it < NIT; ++it) {
        int cur = it & 1;
        if (it + 1 < NIT) {
            stage(it + 1, cur ^ 1);
            asm volatile("cp.async.commit_group;\n");
            asm volatile("cp.async.wait_group 1;\n");
        } else {
            asm volatile("cp.async.wait_group 0;\n");
        }
        __syncthreads();

        const float* raw = (const float*)(smem + OFF_RAW + cur * 16896);
        uint32_t* Ap = (uint32_t*)(smem + OFF_A + cur * 4352);
        const uint32_t* yq = (const uint32_t*)(smem + OFF_YQ + cur * 32);

        // ---- quantize membership -> Apack[nq][m] + dp4a mass/wy ----
#pragma unroll
        for (int q = 0; q < 4; ++q) {
            int nql = 4 * h + q;
            int nb = nql * 4;
            uint32_t pk = pack4(q255(raw[(nb + 0) * 132 + m_own]),
                                q255(raw[(nb + 1) * 132 + m_own]),
                                q255(raw[(nb + 2) * 132 + m_own]),
                                q255(raw[(nb + 3) * 132 + m_own]));
            Ap[nql * 136 + m_own] = pk;
            massI = dp4a_u(pk, 0x01010101u, massI);
            wyI = dp4a_u(pk, yq[nql], wyI);
        }
        __syncthreads();

        // ---- 16 u8 IMMAs (m32 x c64 per warp, k=32) ----
        const uint32_t* Bp = (const uint32_t*)(smem + OFF_B + cur * 4352);
        uint32_t a[2][4];
#pragma unroll
        for (int mt2 = 0; mt2 < 2; ++mt2) {
            int mr = m_off + mt2 * 16 + lr;
            a[mt2][0] = Ap[lc * 136 + mr];
            a[mt2][1] = Ap[lc * 136 + mr + 8];
            a[mt2][2] = Ap[(lc + 4) * 136 + mr];
            a[mt2][3] = Ap[(lc + 4) * 136 + mr + 8];
        }
#pragma unroll
        for (int ct = 0; ct < 8; ++ct) {
            int cr = c_off + ct * 8 + lr;
            uint32_t b0 = Bp[lc * 136 + cr];
            uint32_t b1 = Bp[(lc + 4) * 136 + cr];
            mma_u8(d[0][ct], a[0], b0, b1);
            mma_u8(d[1][ct], a[1], b0, b1);
        }
        __syncthreads();
    }

    // ---- epilogue ----
    float* Sr = (float*)(smem + OFF_RED);
    Sr[tid] = (float)massI;
    __syncthreads();
    if (tid < 128)
        atomicAdd(&gMass[m0 + tid], ((float)massI + Sr[tid + 128]) * INV255);
    __syncthreads();
    Sr[tid] = (float)wyI;
    __syncthreads();
    if (tid < 128)
        atomicAdd(&gWy[m0 + tid], ((float)wyI + Sr[tid + 128]) * WY_SCALE);

#pragma unroll
    for (int mt2 = 0; mt2 < 2; ++mt2) {
#pragma unroll
        for (int ct = 0; ct < 8; ++ct) {
#pragma unroll
            for (int i = 0; i < 4; ++i) {
                int row = m0 + m_off + mt2 * 16 + lr + ((i >> 1) * 8);
                int col = c_off + ct * 8 + lc * 2 + (i & 1);
                atomicAdd(&gS[(size_t)row * C_DIM + col],
                          (float)d[mt2][ct][i] * INV65025);
            }
        }
    }
}

// ---------------- Kernel 2: per-feature finalize + fused writeout ----------------
__global__ void k2_finalize(float* out, int out_size) {
    __shared__ float cent[K_BINS][C_DIM];
    __shared__ float s_csq[K_BINS];
    __shared__ float wRep[8];
    __shared__ float wInt[8];

    int f = blockIdx.x;
    int tid = threadIdx.x;
    int w = tid >> 5, lane = tid & 31;

    for (int idx = tid; idx < K_BINS * C_DIM; idx += 256) {
        int k = idx >> 7, c = idx & 127;
        float bm = gMass[f * K_BINS + k] + EPSV;
        cent[k][c] = gS[(size_t)(f * K_BINS + k) * C_DIM + c] / bm;
    }
    __syncthreads();

    for (int k = w; k < K_BINS; k += 8) {
        float s = 0.0f;
#pragma unroll
        for (int j = 0; j < 4; ++j) { float v = cent[k][lane + 32 * j]; s += v * v; }
        s = warp_sum(s);
        if (lane == 0) s_csq[k] = s;
    }
    __syncthreads();

    if (w == 0) {
        int k = lane;
        float bm = gMass[f * K_BINS + k] + EPSV;
        float wv = gWy[f * K_BINS + k] / bm - s_csq[k] * (1.0f + EPSV / bm);
        float p = bm / (float)N_SAMPLES;
        float ent = p * logf(p + EPSV);
        float dsum = warp_sum(wv);
        float esum = warp_sum(ent);
        if (lane == 0) { atomicAdd(&gOut[0], dsum); atomicAdd(&gOut[1], esum); }
    }

    float repP = 0.0f;
    for (int p = w; p < K_BINS - 1; p += 8) {
        float s = 0.0f;
#pragma unroll
        for (int j = 0; j < 4; ++j) {
            int c = lane + 32 * j;
            float dd = cent[p][c] - cent[p + 1][c];
            s += dd * dd;
        }
        s = warp_sum(s);
        if (lane == 0) repP += expf(-s);
    }

    float intP = 0.0f;
    for (int k = 0; k < K_BINS - 1; ++k) {
        for (int j = k + 1 + w; j < K_BINS; j += 8) {
            float s = 0.0f;
#pragma unroll
            for (int jj = 0; jj < 4; ++jj) {
                int c = lane + 32 * jj;
                float dd = cent[k][c] - cent[j][c];
                s += dd * dd;
            }
            s = warp_sum(s);
            if (lane == 0) intP += expf(-s);
        }
    }
    if (lane == 0) { wRep[w] = repP; wInt[w] = intP; }
    __syncthreads();

    if (tid == 0) {
        float rep = 0.0f, inter = 0.0f;
        for (int i = 0; i < 8; ++i) { rep += wRep[i]; inter += wInt[i]; }
        atomicAdd(&gOut[2], rep);
        atomicAdd(&gOut[3], inter);
        __threadfence();
        int done = atomicAdd(&gDone, 1);
        if (done == F_DIM - 1) {
            float disp  = atomicAdd(&gOut[0], 0.0f);
            float ent   = atomicAdd(&gOut[1], 0.0f);
            float repT  = atomicAdd(&gOut[2], 0.0f);
            float intT  = atomicAdd(&gOut[3], 0.0f) / (float)F_DIM;
            float total = disp + 0.1f * ent + 0.5f * repT + 0.3f * intT;
            float vals[5] = {total, disp, ent, repT, intT};
            for (int i = 0; i < out_size; ++i) out[i] = (i < 5) ? vals[i] : 0.0f;
        }
    }
}

extern "C" void kernel_launch(void* const* d_in, const int* in_sizes, int n_in,
                              void* d_out, int out_size) {
    const float* p0 = (const float*)d_in[0];
    const float* p1 = (const float*)d_in[1];
    const float* membership = p0;
    const float* teacher = p1;
    if (n_in >= 2 && in_sizes[0] < in_sizes[1]) { membership = p1; teacher = p0; }
    cudaFuncSetAttribute(k1_main, cudaFuncAttributeMaxDynamicSharedMemorySize, SMEM_K1);
    k0_init<<<256, 256>>>(teacher);
    k1_main<<<SPLITS * 16, 256, SMEM_K1>>>(membership);
    k2_finalize<<<F_DIM, 256>>>((float*)d_out, out_size);
}